// round 1
// baseline (speedup 1.0000x reference)
#include <cuda_runtime.h>
#include <math.h>

#define N_CAPS 64
#define IN_CAPS 4096
#define CAP_DIM 32
#define IN_DIM 16
#define NUM_ROUTINGS 3
#define EPS 1e-7f

// Scratch (allocation-free rule: __device__ globals)
__device__ float g_u[(size_t)N_CAPS * IN_CAPS * CAP_DIM];   // 33.5 MB
__device__ float g_logits[N_CAPS * IN_CAPS];                // 1 MB
__device__ float g_s[N_CAPS * CAP_DIM];
__device__ float g_v[N_CAPS * CAP_DIM];

// ---------------------------------------------------------------------------
// Zero logits and v (must run every launch: deterministic replay)
// ---------------------------------------------------------------------------
__global__ void zero_kernel() {
    int idx = blockIdx.x * blockDim.x + threadIdx.x;
    if (idx < N_CAPS * IN_CAPS) g_logits[idx] = 0.0f;
    if (idx < N_CAPS * CAP_DIM) g_v[idx] = 0.0f;
}

// ---------------------------------------------------------------------------
// u[n,i,d] = sum_k W[n,i,d,k] * x[i,k]
// One warp per (n,i); lane = d. Each lane reads its contiguous 64B of W
// (4 x float4) -> warp covers a contiguous 2KB region. HBM-bound on W.
// ---------------------------------------------------------------------------
__global__ __launch_bounds__(256) void uhat_kernel(const float* __restrict__ W,
                                                   const float* __restrict__ x) {
    int w = blockIdx.x * (blockDim.x >> 5) + (threadIdx.x >> 5);  // (n,i) pair
    int lane = threadIdx.x & 31;                                  // d
    if (w >= N_CAPS * IN_CAPS) return;
    int i = w & (IN_CAPS - 1);

    const float4* xp = reinterpret_cast<const float4*>(x + (size_t)i * IN_DIM);
    float4 x0 = xp[0], x1 = xp[1], x2 = xp[2], x3 = xp[3];  // warp-uniform bcast

    const float4* wp = reinterpret_cast<const float4*>(
        W + (((size_t)w * CAP_DIM) + lane) * IN_DIM);
    float4 w0 = wp[0], w1 = wp[1], w2 = wp[2], w3 = wp[3];

    float acc = w0.x * x0.x + w0.y * x0.y + w0.z * x0.z + w0.w * x0.w;
    acc      += w1.x * x1.x + w1.y * x1.y + w1.z * x1.z + w1.w * x1.w;
    acc      += w2.x * x2.x + w2.y * x2.y + w2.z * x2.z + w2.w * x2.w;
    acc      += w3.x * x3.x + w3.y * x3.y + w3.z * x3.z + w3.w * x3.w;

    g_u[(size_t)w * CAP_DIM + lane] = acc;
}

// ---------------------------------------------------------------------------
// Fused routing step for one capsule row n (block = n, 512 threads):
//   logits[n,:] += u[n,:,:] . v_prev        (skipped on first iter; v_prev=0)
//   c = softmax(logits[n,:])                (exp values held in smem)
//   s[n,:] = sum_i c_i * u[n,i,:]
// u passes hit L2 (u = 33.5MB < 126MB L2).
// ---------------------------------------------------------------------------
__global__ __launch_bounds__(512) void route_kernel(int first_iter) {
    const int n = blockIdx.x;
    const int tid = threadIdx.x;
    const int wid = tid >> 5;
    const int lane = tid & 31;

    __shared__ float sm_v[CAP_DIM];
    __shared__ float sm_e[IN_CAPS];       // 16 KB
    __shared__ float sm_red[16];
    __shared__ float sm_bcast;
    __shared__ float sm_part[16][CAP_DIM];

    if (tid < CAP_DIM) sm_v[tid] = g_v[n * CAP_DIM + tid];
    __syncthreads();

    const float* __restrict__ urow = g_u + (size_t)n * IN_CAPS * CAP_DIM;
    float* __restrict__ lrow = g_logits + n * IN_CAPS;

    // Pass 1: logits update + stage into smem + row max
    float lmax = -1e30f;
    for (int ii = tid; ii < IN_CAPS; ii += 512) {
        float l = lrow[ii];
        if (!first_iter) {
            const float4* up = reinterpret_cast<const float4*>(urow + (size_t)ii * CAP_DIM);
            float dot = 0.0f;
#pragma unroll
            for (int j = 0; j < 8; j++) {
                float4 u4 = up[j];
                dot += u4.x * sm_v[4 * j + 0] + u4.y * sm_v[4 * j + 1]
                     + u4.z * sm_v[4 * j + 2] + u4.w * sm_v[4 * j + 3];
            }
            l += dot;
            lrow[ii] = l;
        }
        sm_e[ii] = l;
        lmax = fmaxf(lmax, l);
    }
#pragma unroll
    for (int o = 16; o > 0; o >>= 1) lmax = fmaxf(lmax, __shfl_xor_sync(0xffffffffu, lmax, o));
    if (lane == 0) sm_red[wid] = lmax;
    __syncthreads();
    if (tid == 0) {
        float m = sm_red[0];
#pragma unroll
        for (int k = 1; k < 16; k++) m = fmaxf(m, sm_red[k]);
        sm_bcast = m;
    }
    __syncthreads();
    const float rowmax = sm_bcast;
    __syncthreads();

    // Pass 2 (smem-only): exponentiate + row sum
    float lsum = 0.0f;
    for (int ii = tid; ii < IN_CAPS; ii += 512) {
        float e = __expf(sm_e[ii] - rowmax);
        sm_e[ii] = e;
        lsum += e;
    }
#pragma unroll
    for (int o = 16; o > 0; o >>= 1) lsum += __shfl_xor_sync(0xffffffffu, lsum, o);
    if (lane == 0) sm_red[wid] = lsum;
    __syncthreads();
    if (tid == 0) {
        float s = 0.0f;
#pragma unroll
        for (int k = 0; k < 16; k++) s += sm_red[k];
        sm_bcast = s;
    }
    __syncthreads();
    const float inv = 1.0f / sm_bcast;

    // Pass 3: s[n,d] = sum_i c_i * u[n,i,d]
    float acc[CAP_DIM];
#pragma unroll
    for (int d = 0; d < CAP_DIM; d++) acc[d] = 0.0f;

    for (int ii = tid; ii < IN_CAPS; ii += 512) {
        float c = sm_e[ii] * inv;
        const float4* up = reinterpret_cast<const float4*>(urow + (size_t)ii * CAP_DIM);
#pragma unroll
        for (int j = 0; j < 8; j++) {
            float4 u4 = up[j];
            acc[4 * j + 0] += c * u4.x;
            acc[4 * j + 1] += c * u4.y;
            acc[4 * j + 2] += c * u4.z;
            acc[4 * j + 3] += c * u4.w;
        }
    }
#pragma unroll
    for (int d = 0; d < CAP_DIM; d++) {
#pragma unroll
        for (int o = 16; o > 0; o >>= 1) acc[d] += __shfl_xor_sync(0xffffffffu, acc[d], o);
    }
    if (lane == 0) {
#pragma unroll
        for (int d = 0; d < CAP_DIM; d++) sm_part[wid][d] = acc[d];
    }
    __syncthreads();
    if (tid < CAP_DIM) {
        float s = 0.0f;
#pragma unroll
        for (int k = 0; k < 16; k++) s += sm_part[k][tid];
        g_s[n * CAP_DIM + tid] = s;
    }
}

// ---------------------------------------------------------------------------
// Squash (FAITHFUL to source: global sum over ALL axes):
//   sq = sum(s*s); v = s * sq/(1+sq)/(sqrt(sq)+eps)
// Single block. Writes v to g_v, and (last iter) also to d_out.
// ---------------------------------------------------------------------------
__global__ __launch_bounds__(256) void squash_kernel(float* __restrict__ out) {
    const int tid = threadIdx.x;
    const int wid = tid >> 5;
    const int lane = tid & 31;
    __shared__ float sm_red[8];
    __shared__ float sm_bcast;

    float sq = 0.0f;
    for (int idx = tid; idx < N_CAPS * CAP_DIM; idx += 256) {
        float s = g_s[idx];
        sq += s * s;
    }
#pragma unroll
    for (int o = 16; o > 0; o >>= 1) sq += __shfl_xor_sync(0xffffffffu, sq, o);
    if (lane == 0) sm_red[wid] = sq;
    __syncthreads();
    if (tid == 0) {
        float t = 0.0f;
#pragma unroll
        for (int k = 0; k < 8; k++) t += sm_red[k];
        sm_bcast = t;
    }
    __syncthreads();
    const float total = sm_bcast;
    const float scale = total / (1.0f + total) / (sqrtf(total) + EPS);

    for (int idx = tid; idx < N_CAPS * CAP_DIM; idx += 256) {
        float v = g_s[idx] * scale;
        g_v[idx] = v;
        if (out) out[idx] = v;
    }
}

// ---------------------------------------------------------------------------
extern "C" void kernel_launch(void* const* d_in, const int* in_sizes, int n_in,
                              void* d_out, int out_size) {
    // metadata order: input_data (65536 floats), W (134217728 floats).
    // Detect by size for safety.
    const float* x = (const float*)d_in[0];
    const float* W = (const float*)d_in[1];
    if (in_sizes[0] > in_sizes[1]) {
        const float* t = x; x = W; W = t;
    }
    float* out = (float*)d_out;

    zero_kernel<<<(N_CAPS * IN_CAPS + 255) / 256, 256>>>();

    const int pairs = N_CAPS * IN_CAPS;            // 262144 warps
    uhat_kernel<<<pairs / 8, 256>>>(W, x);         // 8 warps per block

    for (int t = 0; t < NUM_ROUTINGS; t++) {
        route_kernel<<<N_CAPS, 512>>>(t == 0 ? 1 : 0);
        squash_kernel<<<1, 256>>>(t == NUM_ROUTINGS - 1 ? out : nullptr);
    }
}

// round 2
// speedup vs baseline: 1.3485x; 1.3485x over previous
#include <cuda_runtime.h>
#include <math.h>

#define N_CAPS 64
#define IN_CAPS 4096
#define CAP_DIM 32
#define IN_DIM 16
#define NUM_ROUTINGS 3
#define EPS 1e-7f
#define CHUNKS 16
#define CHUNK_I (IN_CAPS / CHUNKS)   // 256 inputs per scan block (1 per thread)

// Scratch (__device__ globals: allocation-free rule)
__device__ float g_u[(size_t)N_CAPS * IN_CAPS * CAP_DIM];     // 33.5 MB
__device__ float g_vcum[N_CAPS * CAP_DIM];                    // sum of v over past iters
__device__ float g_pm[N_CAPS * CHUNKS];                       // partial max
__device__ float g_pz[N_CAPS * CHUNKS];                       // partial sum exp
__device__ float g_ps[N_CAPS * CHUNKS * CAP_DIM];             // partial weighted u sums

// ---------------------------------------------------------------------------
__global__ void zero_kernel() {
    int idx = blockIdx.x * blockDim.x + threadIdx.x;
    if (idx < N_CAPS * CAP_DIM) g_vcum[idx] = 0.0f;
}

// ---------------------------------------------------------------------------
// u[n,i,d] = sum_k W[n,i,d,k] * x[i,k]
// One warp per (n,i); lane = d. Warp covers a contiguous 2KB of W. HBM-bound.
// ---------------------------------------------------------------------------
__global__ __launch_bounds__(256) void uhat_kernel(const float* __restrict__ W,
                                                   const float* __restrict__ x) {
    int w = blockIdx.x * (blockDim.x >> 5) + (threadIdx.x >> 5);
    int lane = threadIdx.x & 31;
    int i = w & (IN_CAPS - 1);

    const float4* xp = reinterpret_cast<const float4*>(x + (size_t)i * IN_DIM);
    float4 x0 = xp[0], x1 = xp[1], x2 = xp[2], x3 = xp[3];

    const float4* wp = reinterpret_cast<const float4*>(
        W + (((size_t)w * CAP_DIM) + lane) * IN_DIM);
    float4 w0 = wp[0], w1 = wp[1], w2 = wp[2], w3 = wp[3];

    float acc = w0.x * x0.x + w0.y * x0.y + w0.z * x0.z + w0.w * x0.w;
    acc      += w1.x * x1.x + w1.y * x1.y + w1.z * x1.z + w1.w * x1.w;
    acc      += w2.x * x2.x + w2.y * x2.y + w2.z * x2.z + w2.w * x2.w;
    acc      += w3.x * x3.x + w3.y * x3.y + w3.z * x3.z + w3.w * x3.w;

    g_u[(size_t)w * CAP_DIM + lane] = acc;
}

// ---------------------------------------------------------------------------
// Routing scan: one pass over u per iteration.
// Block = (chunk, n), 256 threads, 1 input-capsule per thread.
//   l_i = u_i . V_cum ; M = max l ; e_i = exp(l_i - M)
//   partials: M, Z = sum e, S[d] = sum e*u_i[d]
// ---------------------------------------------------------------------------
__global__ __launch_bounds__(256) void scan_kernel() {
    const int n = blockIdx.y;
    const int chunk = blockIdx.x;
    const int tid = threadIdx.x;
    const int wid = tid >> 5;
    const int lane = tid & 31;

    __shared__ float sm_v[CAP_DIM];
    __shared__ float sm_wred[8];
    __shared__ float sm_wvec[8][CAP_DIM];
    __shared__ float sm_bcast;

    if (tid < CAP_DIM) sm_v[tid] = g_vcum[n * CAP_DIM + tid];
    __syncthreads();

    const int i = chunk * CHUNK_I + tid;
    const float4* up = reinterpret_cast<const float4*>(
        g_u + ((size_t)n * IN_CAPS + i) * CAP_DIM);

    float4 U[8];
#pragma unroll
    for (int j = 0; j < 8; j++) U[j] = up[j];

    float l = 0.0f;
#pragma unroll
    for (int j = 0; j < 8; j++) {
        l += U[j].x * sm_v[4 * j + 0] + U[j].y * sm_v[4 * j + 1]
           + U[j].z * sm_v[4 * j + 2] + U[j].w * sm_v[4 * j + 3];
    }

    // block max
    float m = l;
#pragma unroll
    for (int o = 16; o > 0; o >>= 1) m = fmaxf(m, __shfl_xor_sync(0xffffffffu, m, o));
    if (lane == 0) sm_wred[wid] = m;
    __syncthreads();
    if (tid == 0) {
        float mm = sm_wred[0];
#pragma unroll
        for (int k = 1; k < 8; k++) mm = fmaxf(mm, sm_wred[k]);
        sm_bcast = mm;
    }
    __syncthreads();
    const float M = sm_bcast;

    float e = __expf(l - M);

    // scale U in place: U = e * u_i  (this is this thread's contribution to S)
#pragma unroll
    for (int j = 0; j < 8; j++) {
        U[j].x *= e; U[j].y *= e; U[j].z *= e; U[j].w *= e;
    }

    // warp reduce Z and the 32-dim vector
    float z = e;
#pragma unroll
    for (int o = 16; o > 0; o >>= 1) z += __shfl_xor_sync(0xffffffffu, z, o);

#pragma unroll
    for (int j = 0; j < 8; j++) {
#pragma unroll
        for (int o = 16; o > 0; o >>= 1) {
            U[j].x += __shfl_xor_sync(0xffffffffu, U[j].x, o);
            U[j].y += __shfl_xor_sync(0xffffffffu, U[j].y, o);
            U[j].z += __shfl_xor_sync(0xffffffffu, U[j].z, o);
            U[j].w += __shfl_xor_sync(0xffffffffu, U[j].w, o);
        }
    }
    if (lane == 0) {
        sm_wred[wid] = z;
#pragma unroll
        for (int j = 0; j < 8; j++) {
            sm_wvec[wid][4 * j + 0] = U[j].x;
            sm_wvec[wid][4 * j + 1] = U[j].y;
            sm_wvec[wid][4 * j + 2] = U[j].z;
            sm_wvec[wid][4 * j + 3] = U[j].w;
        }
    }
    __syncthreads();

    const int slot = n * CHUNKS + chunk;
    if (tid == 0) {
        float zt = 0.0f;
#pragma unroll
        for (int k = 0; k < 8; k++) zt += sm_wred[k];
        g_pm[slot] = M;
        g_pz[slot] = zt;
    }
    if (tid < CAP_DIM) {
        float s = 0.0f;
#pragma unroll
        for (int k = 0; k < 8; k++) s += sm_wvec[k][tid];
        g_ps[slot * CAP_DIM + tid] = s;
    }
}

// ---------------------------------------------------------------------------
// Combine: merge partials -> softmax-normalized s[n,:], global squash,
// update V_cum, optionally write output. Single block, 1024 threads.
// ---------------------------------------------------------------------------
__global__ __launch_bounds__(1024) void combine_kernel(float* __restrict__ out) {
    const int tid = threadIdx.x;          // tid = n*16 + c  (64 x 16 = 1024)
    const int wid = tid >> 5;
    const int lane = tid & 31;

    __shared__ float sm_w[N_CAPS * CHUNKS];   // exp(m_c - M_n)
    __shared__ float sm_Z[N_CAPS];
    __shared__ float sm_s[N_CAPS * CAP_DIM];  // 2048 floats
    __shared__ float sm_red[32];
    __shared__ float sm_bcast;

    {
        float m = g_pm[tid];
        float z = g_pz[tid];
        float M = m;
#pragma unroll
        for (int o = 8; o > 0; o >>= 1) M = fmaxf(M, __shfl_xor_sync(0xffffffffu, M, o, 16));
        float w = __expf(m - M);
        float zw = z * w;
#pragma unroll
        for (int o = 8; o > 0; o >>= 1) zw += __shfl_xor_sync(0xffffffffu, zw, o, 16);
        sm_w[tid] = w;
        if ((tid & 15) == 0) sm_Z[tid >> 4] = zw;
    }
    __syncthreads();

    // s[n,d] = (sum_c w_c * S[n,c,d]) / Z_n ;  accumulate global sq = sum s^2
    float sq = 0.0f;
#pragma unroll
    for (int r = 0; r < 2; r++) {
        int idx = tid + r * 1024;          // idx = n*32 + d
        int n2 = idx >> 5;
        int d = idx & 31;
        float s = 0.0f;
#pragma unroll
        for (int c = 0; c < CHUNKS; c++) {
            s += sm_w[n2 * CHUNKS + c] * g_ps[(n2 * CHUNKS + c) * CAP_DIM + d];
        }
        s /= sm_Z[n2];
        sm_s[idx] = s;
        sq += s * s;
    }
#pragma unroll
    for (int o = 16; o > 0; o >>= 1) sq += __shfl_xor_sync(0xffffffffu, sq, o);
    if (lane == 0) sm_red[wid] = sq;
    __syncthreads();
    if (tid == 0) {
        float t = 0.0f;
#pragma unroll
        for (int k = 0; k < 32; k++) t += sm_red[k];
        sm_bcast = t;
    }
    __syncthreads();
    const float total = sm_bcast;
    const float scale = total / (1.0f + total) / (sqrtf(total) + EPS);

#pragma unroll
    for (int r = 0; r < 2; r++) {
        int idx = tid + r * 1024;
        float v = sm_s[idx] * scale;
        g_vcum[idx] += v;
        if (out) out[idx] = v;
    }
}

// ---------------------------------------------------------------------------
extern "C" void kernel_launch(void* const* d_in, const int* in_sizes, int n_in,
                              void* d_out, int out_size) {
    const float* x = (const float*)d_in[0];
    const float* W = (const float*)d_in[1];
    if (in_sizes[0] > in_sizes[1]) { const float* t = x; x = W; W = t; }
    float* out = (float*)d_out;

    zero_kernel<<<(N_CAPS * CAP_DIM + 255) / 256, 256>>>();

    const int pairs = N_CAPS * IN_CAPS;
    uhat_kernel<<<pairs / 8, 256>>>(W, x);

    dim3 scan_grid(CHUNKS, N_CAPS);
    for (int t = 0; t < NUM_ROUTINGS; t++) {
        scan_kernel<<<scan_grid, 256>>>();
        combine_kernel<<<1, 1024>>>(t == NUM_ROUTINGS - 1 ? out : nullptr);
    }
}